// round 11
// baseline (speedup 1.0000x reference)
#include <cuda_runtime.h>

// crossCorrelation3D: local 9x9 windowed cross-correlation loss.
// input (32,1,512,512) fp32, target (32,1,512,512) fp32 -> scalar.
//
// Vertical-first separable box sums, single fused kernel:
//   - 5 vertical running sums (I,T,II,TT,IT) in registers (f32x2 packed).
//   - row y-9 subtracted by reloading from global (L1-resident), guarded.
//   - horizontal 9-sum via shared exchange; 2 rows per __syncthreads using
//     pair-parity double buffering (4 buffers, 41.6 KB).
//   - final reduction fused via last-CTA pattern (fixed-order -> deterministic).
// Grid = 16 ytiles x 32 batches = 512 CTAs, 128 thr x 4 cols, occ 4 (1 wave).

#define IMG_W 512
#define IMG_H 512
#define NB    32
#define HT    32
#define YT    16
#define NT    128
#define CSTRIDE 520         // 4 pad + 512 + 4 pad
#define BUFF  (5*CSTRIDE)   // one exchange buffer (5 channels)
#define NPART (YT*NB)       // 512

__device__ float g_part[NPART];
__device__ unsigned g_cnt = 0;

// ---- packed f32x2 helpers ----
struct F2 { unsigned long long v; };

__device__ __forceinline__ F2 f2pk(float lo, float hi) {
    F2 r; asm("mov.b64 %0,{%1,%2};" : "=l"(r.v) : "f"(lo), "f"(hi)); return r;
}
__device__ __forceinline__ void f2up(F2 a, float& lo, float& hi) {
    asm("mov.b64 {%0,%1},%2;" : "=f"(lo), "=f"(hi) : "l"(a.v));
}
__device__ __forceinline__ F2 add2(F2 a, F2 b) {
    F2 r; asm("add.rn.f32x2 %0,%1,%2;" : "=l"(r.v) : "l"(a.v), "l"(b.v)); return r;
}
__device__ __forceinline__ F2 mul2(F2 a, F2 b) {
    F2 r; asm("mul.rn.f32x2 %0,%1,%2;" : "=l"(r.v) : "l"(a.v), "l"(b.v)); return r;
}
__device__ __forceinline__ F2 fma2(F2 a, F2 b, F2 c) {
    F2 r; asm("fma.rn.f32x2 %0,%1,%2,%3;" : "=l"(r.v) : "l"(a.v), "l"(b.v), "l"(c.v)); return r;
}
__device__ __forceinline__ F2 sub2(F2 a, F2 b, F2 neg1) { return fma2(b, neg1, a); }
__device__ __forceinline__ F2 f2z() { F2 r; r.v = 0ull; return r; }

// Load one row pair (I raw, T normalized). Valid iff ymin <= yi < IMG_H.
__device__ __forceinline__ void loadrow(const float* __restrict__ I,
                                        const float* __restrict__ T,
                                        int yi, int ymin, int tid, F2 H,
                                        F2& i0, F2& i1, F2& t0, F2& t1) {
    if (yi >= ymin && (unsigned)yi < (unsigned)IMG_H) {
        float4 a = __ldg((const float4*)(I + (size_t)yi * IMG_W) + tid);
        float4 b = __ldg((const float4*)(T + (size_t)yi * IMG_W) + tid);
        i0 = f2pk(a.x, a.y); i1 = f2pk(a.z, a.w);
        t0 = fma2(f2pk(b.x, b.y), H, H);   // (t+1)*0.5
        t1 = fma2(f2pk(b.z, b.w), H, H);
    } else {
        i0 = f2z(); i1 = f2z(); t0 = f2z(); t1 = f2z();
    }
}

// horizontal 9-sum over 12-col window -> 4 outputs as 2 pairs
__device__ __forceinline__ void hsum9p(F2 L0, F2 L1, F2 O0, F2 O1, F2 R0, F2 R1,
                                       F2& hA, F2& hB) {
    F2 Q = add2(add2(L0, L1), add2(O0, O1));
    float qlo, qhi, w0, w1, w2, wx, w8, w9, w10, w11;
    f2up(Q, qlo, qhi);
    f2up(L0, w0, w1);
    f2up(L1, w2, wx);
    f2up(R0, w8, w9);
    f2up(R1, w10, w11);
    float h0 = qlo + qhi + w8;
    float h1 = h0 - w0 + w9;
    float h2 = h1 - w1 + w10;
    float h3 = h2 - w2 + w11;
    hA = f2pk(h0, h1);
    hB = f2pk(h2, h3);
}

__device__ __forceinline__ float cc2(F2 hI, F2 hT, F2 hII, F2 hTT, F2 hIT,
                                     F2 ninv, F2 eps2) {
    F2 cross = fma2(mul2(hI, hT), ninv, hIT);
    F2 tvar  = fma2(mul2(hT, hT), ninv, hTT);
    F2 ivar  = fma2(mul2(hI, hI), ninv, hII);
    F2 den   = fma2(tvar, ivar, eps2);
    F2 num   = mul2(cross, cross);
    float nlo, nhi, dlo, dhi;
    f2up(num, nlo, nhi);
    f2up(den, dlo, dhi);
    return __fdividef(nlo, dlo) + __fdividef(nhi, dhi);
}

struct VS { F2 a0, a1, b0, b1, c0, c1, d0, d1, e0, e1; };

// update vertical sums with one (new,old) row pair
__device__ __forceinline__ void vupdate(VS& v, const float* __restrict__ Ib,
                                        const float* __restrict__ Tb,
                                        int yn, int ymin, int tid, F2 H, F2 NEG1) {
    F2 nI0, nI1, nT0, nT1, oI0, oI1, oT0, oT1;
    loadrow(Ib, Tb, yn, -(1 << 30), tid, H, nI0, nI1, nT0, nT1);
    loadrow(Ib, Tb, yn - 9, ymin, tid, H, oI0, oI1, oT0, oT1);
    v.a0 = add2(v.a0, sub2(nI0, oI0, NEG1));
    v.a1 = add2(v.a1, sub2(nI1, oI1, NEG1));
    v.b0 = add2(v.b0, sub2(nT0, oT0, NEG1));
    v.b1 = add2(v.b1, sub2(nT1, oT1, NEG1));
    v.c0 = add2(v.c0, sub2(mul2(nI0, nI0), mul2(oI0, oI0), NEG1));
    v.c1 = add2(v.c1, sub2(mul2(nI1, nI1), mul2(oI1, oI1), NEG1));
    v.d0 = add2(v.d0, sub2(mul2(nT0, nT0), mul2(oT0, oT0), NEG1));
    v.d1 = add2(v.d1, sub2(mul2(nT1, nT1), mul2(oT1, oT1), NEG1));
    v.e0 = add2(v.e0, sub2(mul2(nI0, nT0), mul2(oI0, oT0), NEG1));
    v.e1 = add2(v.e1, sub2(mul2(nI1, nT1), mul2(oI1, oT1), NEG1));
}

__device__ __forceinline__ void publish(float* buf, const VS& v, int tid) {
    ulonglong2 u;
    u.x = v.a0.v; u.y = v.a1.v; *(ulonglong2*)&buf[0 * CSTRIDE + 4 + 4 * tid] = u;
    u.x = v.b0.v; u.y = v.b1.v; *(ulonglong2*)&buf[1 * CSTRIDE + 4 + 4 * tid] = u;
    u.x = v.c0.v; u.y = v.c1.v; *(ulonglong2*)&buf[2 * CSTRIDE + 4 + 4 * tid] = u;
    u.x = v.d0.v; u.y = v.d1.v; *(ulonglong2*)&buf[3 * CSTRIDE + 4 + 4 * tid] = u;
    u.x = v.e0.v; u.y = v.e1.v; *(ulonglong2*)&buf[4 * CSTRIDE + 4 + 4 * tid] = u;
}

__device__ __forceinline__ float consume(const float* buf, int tid, F2 NINV, F2 EPS2) {
    F2 h[10];
    #pragma unroll
    for (int ch = 0; ch < 5; ch++) {
        ulonglong2 L = *(const ulonglong2*)&buf[ch * CSTRIDE + 4 * tid];
        ulonglong2 O = *(const ulonglong2*)&buf[ch * CSTRIDE + 4 + 4 * tid];
        ulonglong2 R = *(const ulonglong2*)&buf[ch * CSTRIDE + 8 + 4 * tid];
        F2 l0, l1, o0, o1, r0, r1;
        l0.v = L.x; l1.v = L.y; o0.v = O.x; o1.v = O.y; r0.v = R.x; r1.v = R.y;
        hsum9p(l0, l1, o0, o1, r0, r1, h[2 * ch], h[2 * ch + 1]);
    }
    return cc2(h[0], h[2], h[4], h[6], h[8], NINV, EPS2)
         + cc2(h[1], h[3], h[5], h[7], h[9], NINV, EPS2);
}

__global__ __launch_bounds__(NT, 4)
void cc_kernel(const float* __restrict__ inp, const float* __restrict__ tgt,
               float* __restrict__ out) {
    extern __shared__ float sm[];   // 4 * BUFF floats

    const int tid = threadIdx.x;
    const int bx  = blockIdx.x;     // ytile
    const int b   = blockIdx.y;     // batch
    const int y0  = bx * HT;
    const int ymin = y0 - 4;

    const float* Ib = inp + (size_t)b * IMG_H * IMG_W;
    const float* Tb = tgt + (size_t)b * IMG_H * IMG_W;

    // zero the left/right pads of all 4 buffers (5 channels each)
    for (int i = tid; i < 4 * 5 * 8; i += NT) {
        int bf = i / 40, r = i % 40;
        int ch = r / 8, s = r % 8;
        int idx = (s < 4) ? s : (512 + s);
        sm[bf * BUFF + ch * CSTRIDE + idx] = 0.f;
    }
    __syncthreads();

    const F2 H    = f2pk(0.5f, 0.5f);
    const F2 NEG1 = f2pk(-1.f, -1.f);
    const F2 NINV = f2pk(-1.f / 81.f, -1.f / 81.f);
    const F2 EPS2 = f2pk(1e-5f, 1e-5f);

    VS v; v.a0=f2z(); v.a1=f2z(); v.b0=f2z(); v.b1=f2z(); v.c0=f2z();
    v.c1=f2z(); v.d0=f2z(); v.d1=f2z(); v.e0=f2z(); v.e1=f2z();
    float acc = 0.f;

    // halo: accumulate rows y0-4 .. y0+3 (no output)
    #pragma unroll
    for (int it = 0; it < 8; ++it)
        vupdate(v, Ib, Tb, y0 - 4 + it, ymin, tid, H, NEG1);

    // 16 pairs of output rows; one barrier per pair via pair-parity buffers
    for (int p = 0; p < HT / 2; ++p) {
        float* bufA = sm + ((p & 1) * 2 + 0) * BUFF;
        float* bufB = sm + ((p & 1) * 2 + 1) * BUFF;

        vupdate(v, Ib, Tb, y0 + 4 + 2 * p, ymin, tid, H, NEG1);
        publish(bufA, v, tid);
        vupdate(v, Ib, Tb, y0 + 5 + 2 * p, ymin, tid, H, NEG1);
        publish(bufB, v, tid);
        __syncthreads();

        acc += consume(bufA, tid, NINV, EPS2);
        acc += consume(bufB, tid, NINV, EPS2);
    }

    // block reduction (reuse exchange buffer)
    __syncthreads();
    sm[tid] = acc;
    __syncthreads();
    #pragma unroll
    for (int s = NT / 2; s > 0; s >>= 1) {
        if (tid < s) sm[tid] += sm[tid + s];
        __syncthreads();
    }

    // fused finalize: last CTA reduces all partials in fixed order
    __shared__ unsigned s_last;
    if (tid == 0) {
        g_part[b * YT + bx] = sm[0];
        __threadfence();
        unsigned r = atomicAdd(&g_cnt, 1u);
        s_last = (r == NPART - 1) ? 1u : 0u;
    }
    __syncthreads();
    if (s_last) {
        float t = 0.f;
        #pragma unroll
        for (int k = 0; k < NPART / NT; k++)      // fixed order -> deterministic
            t += g_part[tid + k * NT];
        sm[tid] = t;
        __syncthreads();
        #pragma unroll
        for (int s = NT / 2; s > 0; s >>= 1) {
            if (tid < s) sm[tid] += sm[tid + s];
            __syncthreads();
        }
        if (tid == 0) {
            out[0] = -sm[0] * (1.0f / 8388608.0f);
            g_cnt = 0;   // reset for next graph replay
        }
    }
}

extern "C" void kernel_launch(void* const* d_in, const int* in_sizes, int n_in,
                              void* d_out, int out_size) {
    const float* inp = (const float*)d_in[0];
    const float* tgt = (const float*)d_in[1];
    size_t smem = (size_t)(4 * BUFF) * sizeof(float);   // 41.6 KB
    cudaFuncSetAttribute(cc_kernel, cudaFuncAttributeMaxDynamicSharedMemorySize, (int)smem);
    dim3 grid(YT, NB);   // (16, 32) = 512 CTAs, one wave at occ 4
    cc_kernel<<<grid, NT, smem>>>(inp, tgt, (float*)d_out);
}